// round 3
// baseline (speedup 1.0000x reference)
#include <cuda_runtime.h>
#include <cstdint>

// DiverseSiblingsSearch on GB300.
// lprobs: (128, 5, 50257) f32, scores: (128, 5, 10) f32, step: int scalar (=10).
// Output (f32, concatenated): final_scores (128,10) | final_indices (128,10) | final_beams (128,10).

#define BSZ     128
#define BEAM    5
#define VOCAB   50257
#define KSEL    10
#define ROWS    (BSZ * BEAM)
#define THREADS 256
#define DIV_RATE 0.5f

#define NEG_INF __int_as_float(0xff800000u)

// Scratch for inter-kernel candidates (no allocations allowed).
__device__ float g_cand_val[ROWS * KSEL];
__device__ int   g_cand_idx[ROWS * KSEL];

__device__ __forceinline__ bool better(float v1, int i1, float v2, int i2) {
    // JAX top_k stability: larger value wins; ties -> smaller index wins.
    return (v1 > v2) || (v1 == v2 && i1 < i2);
}

__device__ __forceinline__ void insert10(float v, int ix, float (&val)[KSEL], int (&idq)[KSEL]) {
    if (!better(v, ix, val[KSEL - 1], idq[KSEL - 1])) return;
    val[KSEL - 1] = v;
    idq[KSEL - 1] = ix;
#pragma unroll
    for (int j = KSEL - 1; j > 0; --j) {
        if (better(val[j], idq[j], val[j - 1], idq[j - 1])) {
            float tv = val[j]; val[j] = val[j - 1]; val[j - 1] = tv;
            int   ti = idq[j]; idq[j] = idq[j - 1]; idq[j - 1] = ti;
        }
    }
}

__global__ __launch_bounds__(THREADS)
void topk_per_beam_kernel(const float* __restrict__ lprobs,
                          const float* __restrict__ scores,
                          const int* __restrict__ step_ptr,
                          int score_last_dim) {
    const int row = blockIdx.x;                 // row = b * BEAM + beam
    const int tid = threadIdx.x;
    const float* __restrict__ rp = lprobs + (size_t)row * VOCAB;

    float val[KSEL];
    int   idq[KSEL];
#pragma unroll
    for (int j = 0; j < KSEL; ++j) { val[j] = NEG_INF; idq[j] = 0x7fffffff; }

    // Strided scan, 4x unrolled for MLP. Common path: 1 LDG + 1 compare.
    int i = tid;
    for (; i + 3 * THREADS < VOCAB; i += 4 * THREADS) {
        float v0 = rp[i];
        float v1 = rp[i + THREADS];
        float v2 = rp[i + 2 * THREADS];
        float v3 = rp[i + 3 * THREADS];
        if (better(v0, i,               val[KSEL - 1], idq[KSEL - 1])) insert10(v0, i,               val, idq);
        if (better(v1, i + THREADS,     val[KSEL - 1], idq[KSEL - 1])) insert10(v1, i + THREADS,     val, idq);
        if (better(v2, i + 2 * THREADS, val[KSEL - 1], idq[KSEL - 1])) insert10(v2, i + 2 * THREADS, val, idq);
        if (better(v3, i + 3 * THREADS, val[KSEL - 1], idq[KSEL - 1])) insert10(v3, i + 3 * THREADS, val, idq);
    }
    for (; i < VOCAB; i += THREADS) {
        float v = rp[i];
        if (better(v, i, val[KSEL - 1], idq[KSEL - 1])) insert10(v, i, val, idq);
    }

    // Merge tree: 256 sorted 10-lists -> 1 sorted 10-list. Padded smem (stride 11) is
    // conflict-free (gcd(11,32)=1). A thread active at step `half` was active at all
    // larger halves, so its register list is always current; write-back keeps smem
    // rows current for when a thread later becomes a merge source.
    __shared__ float sval[THREADS][KSEL + 1];
    __shared__ int   sidx[THREADS][KSEL + 1];
#pragma unroll
    for (int j = 0; j < KSEL; ++j) { sval[tid][j] = val[j]; sidx[tid][j] = idq[j]; }

    for (int half = THREADS / 2; half >= 1; half >>= 1) {
        __syncthreads();
        if (tid < half) {
#pragma unroll
            for (int j = 0; j < KSEL; ++j) {
                float v  = sval[tid + half][j];
                int   ix = sidx[tid + half][j];
                if (better(v, ix, val[KSEL - 1], idq[KSEL - 1])) insert10(v, ix, val, idq);
            }
#pragma unroll
            for (int j = 0; j < KSEL; ++j) { sval[tid][j] = val[j]; sidx[tid][j] = idq[j]; }
        }
    }

    if (tid == 0) {
        const int stepv = step_ptr ? *step_ptr : 10;
        const float base = scores[row * score_last_dim + (stepv - 1)];
#pragma unroll
        for (int r = 0; r < KSEL; ++r) {
            // ((lprob + base) - penalty): same op order as reference -> bit-exact.
            g_cand_val[row * KSEL + r] = (val[r] + base) - (float)(r + 1) * DIV_RATE;
            g_cand_idx[row * KSEL + r] = idq[r];
        }
    }
}

__global__ void final_topk_kernel(float* __restrict__ out) {
    const int b = blockIdx.x;
    const int tid = threadIdx.x;
    __shared__ float cv[BEAM * KSEL];
    __shared__ int   ci[BEAM * KSEL];

    if (tid < BEAM * KSEL) {
        cv[tid] = g_cand_val[b * BEAM * KSEL + tid];
        ci[tid] = g_cand_idx[b * BEAM * KSEL + tid];
    }
    __syncthreads();

    if (tid == 0) {
        // Stable top-10 over 50: strict '>' keeps the smallest flat position on ties,
        // matching JAX top_k over the flattened (beam*k) axis.
        for (int r = 0; r < KSEL; ++r) {
            float bv = NEG_INF;
            int   bp = 0;
            for (int p = 0; p < BEAM * KSEL; ++p) {
                if (cv[p] > bv) { bv = cv[p]; bp = p; }
            }
            out[b * KSEL + r]                    = bv;                      // final_scores
            out[BSZ * KSEL + b * KSEL + r]       = (float)ci[bp];           // final_indices
            out[2 * BSZ * KSEL + b * KSEL + r]   = (float)(bp / KSEL);      // final_beams
            cv[bp] = NEG_INF;
        }
    }
}

extern "C" void kernel_launch(void* const* d_in, const int* in_sizes, int n_in,
                              void* d_out, int out_size) {
    const float* lprobs = (const float*)d_in[0];
    const float* scores = (const float*)d_in[1];
    const int*   step   = (n_in >= 3) ? (const int*)d_in[2] : nullptr;
    const int score_last_dim = in_sizes[1] / ROWS;   // = 10

    topk_per_beam_kernel<<<ROWS, THREADS>>>(lprobs, scores, step, score_last_dim);
    final_topk_kernel<<<BSZ, 64>>>((float*)d_out);
}

// round 5
// speedup vs baseline: 3.7575x; 3.7575x over previous
#include <cuda_runtime.h>
#include <cstdint>

// DiverseSiblingsSearch on GB300 — threshold-select formulation.
// lprobs: (128, 5, 50257) f32, scores: (128, 5, 10) f32, step: int scalar (=10).
// Output (f32): final_scores (128,10) | final_indices (128,10) | final_beams (128,10).

#define BSZ     128
#define BEAM    5
#define VOCAB   50257
#define KSEL    10
#define ROWS    (BSZ * BEAM)
#define T       256
#define NFULL   (VOCAB / T)         // 196 full strided steps
#define CAP     1024
#define DIV_RATE 0.5f
#define NEG_INF __int_as_float(0xff800000u)

// Inter-kernel scratch (no allocations allowed).
__device__ float g_cand_val[ROWS * KSEL];
__device__ int   g_cand_idx[ROWS * KSEL];

__device__ __forceinline__ bool better(float v1, int i1, float v2, int i2) {
    // JAX top_k stability: larger value wins; ties -> smaller index wins.
    return (v1 > v2) || (v1 == v2 && i1 < i2);
}

__global__ __launch_bounds__(T)
void topk_per_beam_kernel(const float* __restrict__ lprobs,
                          const float* __restrict__ scores,
                          const int* __restrict__ step_ptr,
                          int score_last_dim) {
    const int row  = blockIdx.x;               // row = b * BEAM + beam
    const int tid  = threadIdx.x;
    const int lane = tid & 31;
    const float* __restrict__ rp = lprobs + (size_t)row * VOCAB;

    __shared__ float    smax[T];
    __shared__ float    sthresh;
    __shared__ unsigned scount;
    __shared__ float    cval[CAP];
    __shared__ int      cidx[CAP];

    if (tid == 0) scount = 0u;

    // ---- Pass 1: per-thread max, 8 independent accumulators (MLP=8) ----
    float m0 = NEG_INF, m1 = NEG_INF, m2 = NEG_INF, m3 = NEG_INF;
    float m4 = NEG_INF, m5 = NEG_INF, m6 = NEG_INF, m7 = NEG_INF;
    int j = 0;
    for (; j + 7 < NFULL; j += 8) {
        const float* p = rp + tid + j * T;
        float v0 = p[0];     float v1 = p[T];     float v2 = p[2 * T]; float v3 = p[3 * T];
        float v4 = p[4 * T]; float v5 = p[5 * T]; float v6 = p[6 * T]; float v7 = p[7 * T];
        m0 = fmaxf(m0, v0); m1 = fmaxf(m1, v1); m2 = fmaxf(m2, v2); m3 = fmaxf(m3, v3);
        m4 = fmaxf(m4, v4); m5 = fmaxf(m5, v5); m6 = fmaxf(m6, v6); m7 = fmaxf(m7, v7);
    }
    for (; j < NFULL; ++j) m0 = fmaxf(m0, rp[tid + j * T]);
    { int i = tid + NFULL * T; if (i < VOCAB) m0 = fmaxf(m0, rp[i]); }
    smax[tid] = fmaxf(fmaxf(fmaxf(m0, m1), fmaxf(m2, m3)),
                      fmaxf(fmaxf(m4, m5), fmaxf(m6, m7)));
    __syncthreads();

    // ---- Threshold: 10th largest of the 256 per-thread maxima.
    // The 10 largest maxima are 10 distinct elements, so thr <= true 10th
    // largest element of the row -> conservative filter with >= 10 survivors.
    if (tid < 32) {
        for (int r = 0; r < KSEL; ++r) {
            float bv = NEG_INF; int bp = tid;
            for (int c = tid; c < T; c += 32) {
                float v = smax[c];
                if (v > bv) { bv = v; bp = c; }
            }
            for (int off = 16; off; off >>= 1) {
                float ov = __shfl_down_sync(0xffffffffu, bv, off);
                int   op = __shfl_down_sync(0xffffffffu, bp, off);
                if (ov > bv) { bv = ov; bp = op; }
            }
            if (tid == 0) { smax[bp] = NEG_INF; sthresh = bv; }
            __syncwarp();
        }
    }
    __syncthreads();
    const float thr = sthresh;

    // ---- Pass 2: collect candidates >= thr (row mostly L2-resident) ----
    for (j = 0; j + 3 < NFULL; j += 4) {
        const float* p = rp + tid + j * T;
        float v0 = p[0], v1 = p[T], v2 = p[2 * T], v3 = p[3 * T];
#pragma unroll
        for (int u = 0; u < 4; ++u) {
            float v = (u == 0) ? v0 : (u == 1) ? v1 : (u == 2) ? v2 : v3;
            int   i = tid + (j + u) * T;
            bool  pr = (v >= thr);
            unsigned ball = __ballot_sync(0xffffffffu, pr);
            if (ball) {
                int leader = __ffs(ball) - 1;
                unsigned base_ = 0u;
                if (lane == leader) base_ = atomicAdd(&scount, (unsigned)__popc(ball));
                base_ = __shfl_sync(0xffffffffu, base_, leader);
                if (pr) {
                    unsigned pos = base_ + (unsigned)__popc(ball & ((1u << lane) - 1u));
                    if (pos < CAP) { cval[pos] = v; cidx[pos] = i; }
                }
            }
        }
    }
    for (; j <= NFULL; ++j) {           // remainder strided steps + tail step
        int  i   = tid + j * T;
        bool inb = (i < VOCAB);
        float v  = inb ? rp[i] : NEG_INF;
        bool pr  = inb && (v >= thr);
        unsigned ball = __ballot_sync(0xffffffffu, pr);
        if (ball) {
            int leader = __ffs(ball) - 1;
            unsigned base_ = 0u;
            if (lane == leader) base_ = atomicAdd(&scount, (unsigned)__popc(ball));
            base_ = __shfl_sync(0xffffffffu, base_, leader);
            if (pr) {
                unsigned pos = base_ + (unsigned)__popc(ball & ((1u << lane) - 1u));
                if (pos < CAP) { cval[pos] = v; cidx[pos] = i; }
            }
        }
    }
    __syncthreads();

    const unsigned cnt   = scount;
    const int      stepv = step_ptr ? *step_ptr : KSEL;

    if (cnt > CAP) {
        // Pathological (mass ties / -inf rows): exact serial fallback.
        if (tid == 0) {
            float val[KSEL]; int idq[KSEL];
#pragma unroll
            for (int q = 0; q < KSEL; ++q) { val[q] = NEG_INF; idq[q] = 0x7fffffff; }
            for (int i = 0; i < VOCAB; ++i) {
                float v = rp[i];
                if (better(v, i, val[KSEL - 1], idq[KSEL - 1])) {
                    val[KSEL - 1] = v; idq[KSEL - 1] = i;
#pragma unroll
                    for (int q = KSEL - 1; q > 0; --q) {
                        if (better(val[q], idq[q], val[q - 1], idq[q - 1])) {
                            float tv = val[q]; val[q] = val[q - 1]; val[q - 1] = tv;
                            int   ti = idq[q]; idq[q] = idq[q - 1]; idq[q - 1] = ti;
                        }
                    }
                }
            }
            float base = scores[row * score_last_dim + (stepv - 1)];
#pragma unroll
            for (int r = 0; r < KSEL; ++r) {
                g_cand_val[row * KSEL + r] = (val[r] + base) - (float)(r + 1) * DIV_RATE;
                g_cand_idx[row * KSEL + r] = idq[r];
            }
        }
        return;
    }

    // ---- Final per-row top-10 from the candidate buffer (warp 0) ----
    if (tid < 32) {
        float base = scores[row * score_last_dim + (stepv - 1)];
        for (int r = 0; r < KSEL; ++r) {
            float bv = NEG_INF; int bi = 0x7fffffff; int bp = -1;
            for (unsigned c = tid; c < cnt; c += 32) {
                float v = cval[c]; int ix = cidx[c];
                if (better(v, ix, bv, bi)) { bv = v; bi = ix; bp = (int)c; }
            }
            for (int off = 16; off; off >>= 1) {
                float ov = __shfl_down_sync(0xffffffffu, bv, off);
                int   oi = __shfl_down_sync(0xffffffffu, bi, off);
                int   op = __shfl_down_sync(0xffffffffu, bp, off);
                if (better(ov, oi, bv, bi)) { bv = ov; bi = oi; bp = op; }
            }
            if (tid == 0) {
                // ((lprob + base) - penalty): same op order as reference -> bit-exact.
                g_cand_val[row * KSEL + r] = (bv + base) - (float)(r + 1) * DIV_RATE;
                g_cand_idx[row * KSEL + r] = bi;
                cval[bp] = NEG_INF; cidx[bp] = 0x7fffffff;   // retire winner
            }
            __syncwarp();
        }
    }
}

__global__ void final_topk_kernel(float* __restrict__ out) {
    const int b    = blockIdx.x;
    const int lane = threadIdx.x;

    // 50 candidates held in 2 registers/lane; stable on flat position.
    float v0 = NEG_INF, v1 = NEG_INF;
    int   p0 = 0x7fffffff, p1 = 0x7fffffff;
    if (lane < BEAM * KSEL)       { v0 = g_cand_val[b * BEAM * KSEL + lane];      p0 = lane; }
    if (lane + 32 < BEAM * KSEL)  { v1 = g_cand_val[b * BEAM * KSEL + lane + 32]; p1 = lane + 32; }

    for (int r = 0; r < KSEL; ++r) {
        float bv; int bp;
        if (better(v0, p0, v1, p1)) { bv = v0; bp = p0; } else { bv = v1; bp = p1; }
        for (int off = 16; off; off >>= 1) {
            float ov = __shfl_down_sync(0xffffffffu, bv, off);
            int   op = __shfl_down_sync(0xffffffffu, bp, off);
            if (better(ov, op, bv, bp)) { bv = ov; bp = op; }
        }
        bv = __shfl_sync(0xffffffffu, bv, 0);
        bp = __shfl_sync(0xffffffffu, bp, 0);
        if (lane == 0) {
            out[b * KSEL + r]                  = bv;                                        // final_scores
            out[BSZ * KSEL + b * KSEL + r]     = (float)g_cand_idx[b * BEAM * KSEL + bp];   // final_indices
            out[2 * BSZ * KSEL + b * KSEL + r] = (float)(bp / KSEL);                        // final_beams
        }
        if (p0 == bp) { v0 = NEG_INF; p0 = 0x7fffffff; }
        if (p1 == bp) { v1 = NEG_INF; p1 = 0x7fffffff; }
    }
}

extern "C" void kernel_launch(void* const* d_in, const int* in_sizes, int n_in,
                              void* d_out, int out_size) {
    const float* lprobs = (const float*)d_in[0];
    const float* scores = (const float*)d_in[1];
    const int*   step   = (n_in >= 3) ? (const int*)d_in[2] : nullptr;
    const int score_last_dim = in_sizes[1] / ROWS;   // = 10

    topk_per_beam_kernel<<<ROWS, T>>>(lprobs, scores, step, score_last_dim);
    final_topk_kernel<<<BSZ, 32>>>((float*)d_out);
}